// round 11
// baseline (speedup 1.0000x reference)
#include <cuda_runtime.h>

// VectorQuantization: N=32768 rows of D=64 vs K=1024 codes.
// out = [quantized (N*D) | indices as float (N) | commitment_loss (1)]
//
// R11: occupancy push. Thread tile 4 rows x 8 codes (64 acc regs), TPB=256,
// __launch_bounds__(256,2) caps regs at 128 -> 16 warps/SM (vs R10's 8).
// Block = 256 rows x 32 codes, SPL=32 (4096 blocks, 13.8 waves). Warp owns
// 8 codes (all-lane broadcast w loads) x 128 rows; single staging + 1 sync;
// 4-way cross-warp merge over code quarters. Rounding-critical sequences
// identical to all passing rounds (rel_err 1.19e-7).

#define NROWS 32768
#define D     64
#define RB    256                   // rows per block
#define SPL   32                    // K splits
#define KTOT  1024
#define KPB   (KTOT / SPL)          // 32 codes per block
#define TPB   256
#define NBLKM ((NROWS / RB) * SPL)  // 4096
#define EPB   256
#define NEPI  (NROWS / EPB)         // 128

#define SX_BYTES  (32 * RB * 8)     // 65536: x d-pairs [dp][row]
#define SWD_BYTES (32 * KPB * 8)    // 8192:  w d-pairs [dp][code]
#define SXN_OFF   (SX_BYTES + SWD_BYTES)
#define SWN_OFF   (SXN_OFF + RB * 4)
#define SMEM_ALL  (SWN_OFF + KPB * 4)

__device__ float g_best[SPL * NROWS];
__device__ int   g_bidx[SPL * NROWS];
__device__ float g_partial[NEPI];

static __device__ __forceinline__ unsigned long long ffma2(unsigned long long a,
                                                           unsigned long long b,
                                                           unsigned long long c) {
    unsigned long long d;
    asm("fma.rn.f32x2 %0, %1, %2, %3;" : "=l"(d) : "l"(a), "l"(b), "l"(c));
    return d;
}
static __device__ __forceinline__ unsigned long long pack2(float lo, float hi) {
    unsigned long long r;
    asm("mov.b64 %0, {%1, %2};" : "=l"(r) : "f"(lo), "f"(hi));
    return r;
}
static __device__ __forceinline__ void unpack2(unsigned long long v, float& lo, float& hi) {
    asm("mov.b64 {%0, %1}, %2;" : "=f"(lo), "=f"(hi) : "l"(v));
}

// ---- Kernel A: 256-row x 32-code block -------------------------------------
__global__ void __launch_bounds__(TPB, 2) vq_main(const float* __restrict__ x,
                                                  const float* __restrict__ w) {
    extern __shared__ __align__(16) char smem_raw[];
    unsigned long long* sx  = reinterpret_cast<unsigned long long*>(smem_raw);             // [dp][256 rows]
    unsigned long long* swd = reinterpret_cast<unsigned long long*>(smem_raw + SX_BYTES);  // [dp][32 codes]
    float* sxn = reinterpret_cast<float*>(smem_raw + SXN_OFF);   // [RB]
    float* swn = reinterpret_cast<float*>(smem_raw + SWN_OFF);   // [KPB]
    // merge buffers overlay swd (8 KB) after final sync
    float* m_b = reinterpret_cast<float*>(smem_raw + SX_BYTES);             // [4*RB] 4KB
    int*   m_i = reinterpret_cast<int*>(smem_raw + SX_BYTES + 4 * RB * 4);  // [4*RB] 4KB

    const int tid   = threadIdx.x;
    const int lane  = tid & 31;
    const int warp  = tid >> 5;          // 0..7
    const int h     = warp & 1;          // row half (128 rows)
    const int q     = warp >> 1;         // code quarter (8 codes)
    const int split = blockIdx.x & (SPL - 1);
    const int row0  = (blockIdx.x >> 5) * RB;
    const int k0    = split * KPB;

    // ---- stage x row tid (all threads) and w code row tid (tid<32) ----
    {
        const float4* xr = reinterpret_cast<const float4*>(x + (size_t)(row0 + tid) * D);
        float sX = 0.f;
#pragma unroll
        for (int i = 0; i < 16; i++) {
            float4 v = xr[i];
            sX = __fadd_rn(sX, __fmul_rn(v.x, v.x));
            sX = __fadd_rn(sX, __fmul_rn(v.y, v.y));
            sX = __fadd_rn(sX, __fmul_rn(v.z, v.z));
            sX = __fadd_rn(sX, __fmul_rn(v.w, v.w));
            sx[(2 * i) * RB + tid]     = pack2(v.x, v.y);
            sx[(2 * i + 1) * RB + tid] = pack2(v.z, v.w);
        }
        sxn[tid] = sX;
    }
    if (tid < KPB) {
        const float4* wrp = reinterpret_cast<const float4*>(w + (size_t)(k0 + tid) * D);
        float sW = 0.f;
#pragma unroll
        for (int i = 0; i < 16; i++) {
            float4 u = wrp[i];
            sW = __fadd_rn(sW, __fmul_rn(u.x, u.x));
            sW = __fadd_rn(sW, __fmul_rn(u.y, u.y));
            sW = __fadd_rn(sW, __fmul_rn(u.z, u.z));
            sW = __fadd_rn(sW, __fmul_rn(u.w, u.w));
            swd[(2 * i) * KPB + tid]     = pack2(u.x, u.y);
            swd[(2 * i + 1) * KPB + tid] = pack2(u.z, u.w);
        }
        swn[tid] = sW;
    }
    __syncthreads();

    // thread's 4 rows (local): h*128 + 2L, +1, h*128+64+2L, +1
    const int rlA = h * 128 + 2 * lane;
    const int rlB = rlA + 64;
    const float xnr[4] = {sxn[rlA], sxn[rlA + 1], sxn[rlB], sxn[rlB + 1]};

    float bb[4];
    int   bi[4];
#pragma unroll
    for (int r = 0; r < 4; r++) { bb[r] = 3.4e38f; bi[r] = k0; }

    // [dp][128 row-pairs] and [dp][16 code-pairs]
    const ulonglong2* px = reinterpret_cast<const ulonglong2*>(sx) + h * 64;
    const ulonglong2* pw = reinterpret_cast<const ulonglong2*>(swd) + q * 4;

    unsigned long long acc[4][8];
#pragma unroll
    for (int r = 0; r < 4; r++)
#pragma unroll
        for (int c = 0; c < 8; c++) acc[r][c] = 0ull;

#pragma unroll 8
    for (int dp = 0; dp < 32; dp++) {
        // x: 2 spread LDS.128 (32 lanes x contiguous 16B = 512B distinct)
        ulonglong2 xa = px[lane];        // rows h*128+2L, +1
        ulonglong2 xb = px[lane + 32];   // rows h*128+64+2L, +1
        const unsigned long long xv[4] = {xa.x, xa.y, xb.x, xb.y};
        // w: 4 broadcast LDS.128 (all lanes same addr) -> 8 codes
#pragma unroll
        for (int j = 0; j < 4; j++) {
            ulonglong2 wp = pw[j];       // codes q*8+2j, +1
#pragma unroll
            for (int r = 0; r < 4; r++)
                acc[r][2 * j]     = ffma2(xv[r], wp.x, acc[r][2 * j]);
#pragma unroll
            for (int r = 0; r < 4; r++)
                acc[r][2 * j + 1] = ffma2(xv[r], wp.y, acc[r][2 * j + 1]);
        }
        px += 128;   // next dp
        pw += 16;
    }

    // ---- tail: dists + per-thread argmin, codes ascending ----
#pragma unroll
    for (int c = 0; c < 8; c++) {
        const int cl = q * 8 + c;
        const float wn = swn[cl];
        const int cglob = k0 + cl;
#pragma unroll
        for (int r = 0; r < 4; r++) {
            float lo, hi;
            unpack2(acc[r][c], lo, hi);
            float dot = __fadd_rn(lo, hi);
            // Reference rounding: (||x||^2 + ||e||^2) - (2.0 * dot).
            float dist = __fsub_rn(__fadd_rn(xnr[r], wn), __fmul_rn(2.0f, dot));
            if (dist < bb[r]) { bb[r] = dist; bi[r] = cglob; }
        }
    }

    // ---- cross-warp merge over q (code quarters); rows distinct per lane ----
    __syncthreads();  // tails done; safe to overlay swd region
    m_b[q * RB + rlA]     = bb[0];  m_i[q * RB + rlA]     = bi[0];
    m_b[q * RB + rlA + 1] = bb[1];  m_i[q * RB + rlA + 1] = bi[1];
    m_b[q * RB + rlB]     = bb[2];  m_i[q * RB + rlB]     = bi[2];
    m_b[q * RB + rlB + 1] = bb[3];  m_i[q * RB + rlB + 1] = bi[3];
    __syncthreads();
    {
        float B = m_b[tid];
        int   I = m_i[tid];
#pragma unroll
        for (int qq = 1; qq < 4; qq++) {
            float b2 = m_b[qq * RB + tid];
            int   i2 = m_i[qq * RB + tid];
            if (b2 < B || (b2 == B && i2 < I)) { B = b2; I = i2; }  // lowest idx ties
        }
        g_best[split * NROWS + row0 + tid] = B;
        g_bidx[split * NROWS + row0 + tid] = I;
    }
}

// ---- Kernel B: reduce splits, gather, STE output, loss partials ------------
__global__ void __launch_bounds__(EPB) vq_epi(const float* __restrict__ x,
                                              const float* __restrict__ w,
                                              float* __restrict__ out_q,
                                              float* __restrict__ out_idx,
                                              int has_idx) {
    __shared__ float s_red[EPB];
    const int tid = threadIdx.x;
    const int row = blockIdx.x * EPB + tid;

    float best = g_best[row];
    int bidx = g_bidx[row];
#pragma unroll 8
    for (int s = 1; s < SPL; s++) {
        float b = g_best[s * NROWS + row];
        int   i = g_bidx[s * NROWS + row];
        if (b < best) { best = b; bidx = i; }  // strict <: earlier split wins ties
    }

    const float4* wb   = reinterpret_cast<const float4*>(w + (size_t)bidx * D);
    const float4* xrow = reinterpret_cast<const float4*>(x + (size_t)row * D);
    float4* oq = reinterpret_cast<float4*>(out_q + (size_t)row * D);
    float lsum = 0.f;
#pragma unroll
    for (int i = 0; i < 16; i++) {
        float4 wv = wb[i];
        float4 xv = xrow[i];
        float4 dv, ov;
        dv.x = __fsub_rn(wv.x, xv.x);
        dv.y = __fsub_rn(wv.y, xv.y);
        dv.z = __fsub_rn(wv.z, xv.z);
        dv.w = __fsub_rn(wv.w, xv.w);
        ov.x = __fadd_rn(xv.x, dv.x);   // inputs + (quantized - inputs)
        ov.y = __fadd_rn(xv.y, dv.y);
        ov.z = __fadd_rn(xv.z, dv.z);
        ov.w = __fadd_rn(xv.w, dv.w);
        lsum += dv.x * dv.x + dv.y * dv.y + dv.z * dv.z + dv.w * dv.w;
        oq[i] = ov;
    }
    if (has_idx) out_idx[row] = (float)bidx;

    s_red[tid] = lsum;
    __syncthreads();
#pragma unroll
    for (int s = EPB / 2; s > 0; s >>= 1) {
        if (tid < s) s_red[tid] = __fadd_rn(s_red[tid], s_red[tid + s]);
        __syncthreads();
    }
    if (tid == 0) g_partial[blockIdx.x] = s_red[0];
}

// ---- Kernel C: final deterministic reduction -> commitment loss ------------
__global__ void vq_final(float* __restrict__ out_loss) {
    __shared__ float s[64];
    int tid = threadIdx.x;  // 64 threads
    s[tid] = __fadd_rn(g_partial[tid], g_partial[tid + 64]);
    __syncthreads();
    for (int st = 32; st > 0; st >>= 1) {
        if (tid < st) s[tid] = __fadd_rn(s[tid], s[tid + st]);
        __syncthreads();
    }
    if (tid == 0) {
        float mean = s[0] / 2097152.0f;  // exact: power-of-two divisor
        *out_loss = 0.25f * (mean + mean);
    }
}

extern "C" void kernel_launch(void* const* d_in, const int* in_sizes, int n_in,
                              void* d_out, int out_size) {
    const float* x;
    const float* w;
    if (n_in >= 2 && in_sizes[0] == KTOT * D && in_sizes[1] != KTOT * D) {
        w = (const float*)d_in[0];
        x = (const float*)d_in[1];
    } else {
        x = (const float*)d_in[0];
        w = (const float*)d_in[1];
    }

    float* out = (float*)d_out;
    const long ND = (long)NROWS * D;
    if (out_size < ND) return;

    int has_idx  = out_size >= ND + NROWS;
    int has_loss = out_size >= ND + NROWS + 1;

    cudaFuncSetAttribute(vq_main, cudaFuncAttributeMaxDynamicSharedMemorySize, SMEM_ALL);
    vq_main<<<NBLKM, TPB, SMEM_ALL>>>(x, w);
    vq_epi<<<NEPI, EPB>>>(x, w, out, out + ND, has_idx);
    if (has_loss) vq_final<<<1, 64>>>(out + ND + NROWS);
}

// round 12
// speedup vs baseline: 1.0147x; 1.0147x over previous
#include <cuda_runtime.h>

// VectorQuantization: N=32768 rows of D=64 vs K=1024 codes.
// out = [quantized (N*D) | indices as float (N) | commitment_loss (1)]
//
// R12: R10 (best: 113us main) with __launch_bounds__(128,3): caps regs at
// 170 (was 198) so 3 blocks/SM fit (12 warps, 3/SMSP vs 2) -- smem 66KB x3
// = 199KB <= 228KB. Unroll 8->4 to ease pressure. Inner loop mix unchanged
// (64 FFMA2 : 10 LDS per thread-dp). Rounding-critical sequences identical
// to all passing rounds (rel_err 1.19e-7).

#define NROWS 32768
#define D     64
#define RB    128                   // rows per block
#define CBT   64                    // codes per compute tile
#define SPL   8                     // K splits
#define KTOT  1024
#define KPB   (KTOT / SPL)          // 128 codes per block (= 2 tiles, both staged)
#define TILES (KPB / CBT)           // 2
#define TPB   128
#define NBLKM ((NROWS / RB) * SPL)  // 2048
#define EPB   256
#define NEPI  (NROWS / EPB)         // 128

#define SX_BYTES  (32 * RB * 8)     // 32768: x d-pairs [dp][row]
#define SWD_BYTES (32 * KPB * 8)    // 32768: w d-pairs [dp][code]
#define SXN_OFF   (SX_BYTES + SWD_BYTES)
#define SWN_OFF   (SXN_OFF + RB * 4)
#define SMEM_ALL  (SWN_OFF + KPB * 4)

__device__ float g_best[SPL * NROWS];
__device__ int   g_bidx[SPL * NROWS];
__device__ float g_partial[NEPI];

static __device__ __forceinline__ unsigned long long ffma2(unsigned long long a,
                                                           unsigned long long b,
                                                           unsigned long long c) {
    unsigned long long d;
    asm("fma.rn.f32x2 %0, %1, %2, %3;" : "=l"(d) : "l"(a), "l"(b), "l"(c));
    return d;
}
static __device__ __forceinline__ unsigned long long pack2(float lo, float hi) {
    unsigned long long r;
    asm("mov.b64 %0, {%1, %2};" : "=l"(r) : "f"(lo), "f"(hi));
    return r;
}
static __device__ __forceinline__ void unpack2(unsigned long long v, float& lo, float& hi) {
    asm("mov.b64 {%0, %1}, %2;" : "=f"(lo), "=f"(hi) : "l"(v));
}

// ---- Kernel A: 128-row x 128-code block ------------------------------------
__global__ void __launch_bounds__(TPB, 3) vq_main(const float* __restrict__ x,
                                                  const float* __restrict__ w) {
    extern __shared__ __align__(16) char smem_raw[];
    unsigned long long* sx  = reinterpret_cast<unsigned long long*>(smem_raw);             // [dp][128 rows]
    unsigned long long* swd = reinterpret_cast<unsigned long long*>(smem_raw + SX_BYTES);  // [dp][128 codes]
    float* sxn = reinterpret_cast<float*>(smem_raw + SXN_OFF);   // [RB]
    float* swn = reinterpret_cast<float*>(smem_raw + SWN_OFF);   // [KPB]
    // merge buffers overlay swd after final sync
    float* m_b = reinterpret_cast<float*>(smem_raw + SX_BYTES);             // [4*RB]
    int*   m_i = reinterpret_cast<int*>(smem_raw + SX_BYTES + 4 * RB * 4);  // [4*RB]

    const int tid   = threadIdx.x;
    const int lane  = tid & 31;
    const int warp  = tid >> 5;          // 0..3: code chunk warp*16 within tile
    const int split = blockIdx.x & (SPL - 1);
    const int row0  = (blockIdx.x >> 3) * RB;
    const int k0    = split * KPB;

    // ---- stage x row tid AND w code row tid, concurrently; one sync ----
    {
        const float4* xr = reinterpret_cast<const float4*>(x + (size_t)(row0 + tid) * D);
        const float4* wrp = reinterpret_cast<const float4*>(w + (size_t)(k0 + tid) * D);
        float sX = 0.f, sW = 0.f;
#pragma unroll
        for (int i = 0; i < 16; i++) {
            float4 v = xr[i];
            sX = __fadd_rn(sX, __fmul_rn(v.x, v.x));
            sX = __fadd_rn(sX, __fmul_rn(v.y, v.y));
            sX = __fadd_rn(sX, __fmul_rn(v.z, v.z));
            sX = __fadd_rn(sX, __fmul_rn(v.w, v.w));
            sx[(2 * i) * RB + tid]     = pack2(v.x, v.y);
            sx[(2 * i + 1) * RB + tid] = pack2(v.z, v.w);
            float4 u = wrp[i];
            sW = __fadd_rn(sW, __fmul_rn(u.x, u.x));
            sW = __fadd_rn(sW, __fmul_rn(u.y, u.y));
            sW = __fadd_rn(sW, __fmul_rn(u.z, u.z));
            sW = __fadd_rn(sW, __fmul_rn(u.w, u.w));
            swd[(2 * i) * KPB + tid]     = pack2(u.x, u.y);
            swd[(2 * i + 1) * KPB + tid] = pack2(u.z, u.w);
        }
        sxn[tid] = sX;
        swn[tid] = sW;
    }
    __syncthreads();

    // thread's 4 rows: 2*lane, 2*lane+1, 64+2*lane, 65+2*lane
    const int rlA = 2 * lane;
    const int rlB = 64 + 2 * lane;
    const float xnr[4] = {sxn[rlA], sxn[rlA + 1], sxn[rlB], sxn[rlB + 1]};

    float bb[4];
    int   bi[4];
#pragma unroll
    for (int r = 0; r < 4; r++) { bb[r] = 3.4e38f; bi[r] = k0; }

    const ulonglong2* sxu = reinterpret_cast<const ulonglong2*>(sx);   // [dp][64 row-pairs]
    const ulonglong2* swu = reinterpret_cast<const ulonglong2*>(swd);  // [dp][64 code-pairs]

#pragma unroll
    for (int tile = 0; tile < TILES; tile++) {
        const int kt = k0 + tile * CBT;

        unsigned long long acc[4][16];
#pragma unroll
        for (int r = 0; r < 4; r++)
#pragma unroll
            for (int c = 0; c < 16; c++) acc[r][c] = 0ull;

#pragma unroll 4
        for (int dp = 0; dp < 32; dp++) {
            // x: 2 full-spread LDS.128 (lane-contiguous 16B, 512B distinct)
            ulonglong2 xa = sxu[dp * 64 + lane];        // rows 2L, 2L+1
            ulonglong2 xb = sxu[dp * 64 + 32 + lane];   // rows 64+2L, 65+2L
            // w: 8 broadcast LDS.128 (all lanes same addr), 16 codes
#pragma unroll
            for (int j = 0; j < 8; j++) {
                ulonglong2 wp = swu[dp * 64 + tile * 32 + warp * 8 + j];
                acc[0][2 * j]     = ffma2(xa.x, wp.x, acc[0][2 * j]);
                acc[1][2 * j]     = ffma2(xa.y, wp.x, acc[1][2 * j]);
                acc[2][2 * j]     = ffma2(xb.x, wp.x, acc[2][2 * j]);
                acc[3][2 * j]     = ffma2(xb.y, wp.x, acc[3][2 * j]);
                acc[0][2 * j + 1] = ffma2(xa.x, wp.y, acc[0][2 * j + 1]);
                acc[1][2 * j + 1] = ffma2(xa.y, wp.y, acc[1][2 * j + 1]);
                acc[2][2 * j + 1] = ffma2(xb.x, wp.y, acc[2][2 * j + 1]);
                acc[3][2 * j + 1] = ffma2(xb.y, wp.y, acc[3][2 * j + 1]);
            }
        }

        // tail: dists + per-thread argmin, codes ascending
#pragma unroll
        for (int c = 0; c < 16; c++) {
            const int cl = warp * 16 + c;
            const float wn = swn[tile * CBT + cl];
            const int cglob = kt + cl;
#pragma unroll
            for (int r = 0; r < 4; r++) {
                float lo, hi;
                unpack2(acc[r][c], lo, hi);
                float dot = __fadd_rn(lo, hi);
                // Reference rounding: (||x||^2 + ||e||^2) - (2.0 * dot).
                float dist = __fsub_rn(__fadd_rn(xnr[r], wn), __fmul_rn(2.0f, dot));
                if (dist < bb[r]) { bb[r] = dist; bi[r] = cglob; }
            }
        }
    }

    // ---- cross-warp merge (warps own disjoint code chunks, same rows) ----
    __syncthreads();  // tails done; safe to overlay swd region
    m_b[warp * RB + rlA]     = bb[0];  m_i[warp * RB + rlA]     = bi[0];
    m_b[warp * RB + rlA + 1] = bb[1];  m_i[warp * RB + rlA + 1] = bi[1];
    m_b[warp * RB + rlB]     = bb[2];  m_i[warp * RB + rlB]     = bi[2];
    m_b[warp * RB + rlB + 1] = bb[3];  m_i[warp * RB + rlB + 1] = bi[3];
    __syncthreads();
    {
        float B = m_b[tid];
        int   I = m_i[tid];
#pragma unroll
        for (int ww = 1; ww < 4; ww++) {
            float b2 = m_b[ww * RB + tid];
            int   i2 = m_i[ww * RB + tid];
            if (b2 < B || (b2 == B && i2 < I)) { B = b2; I = i2; }  // lowest idx ties
        }
        g_best[split * NROWS + row0 + tid] = B;
        g_bidx[split * NROWS + row0 + tid] = I;
    }
}

// ---- Kernel B: reduce splits, gather, STE output, loss partials ------------
__global__ void __launch_bounds__(EPB) vq_epi(const float* __restrict__ x,
                                              const float* __restrict__ w,
                                              float* __restrict__ out_q,
                                              float* __restrict__ out_idx,
                                              int has_idx) {
    __shared__ float s_red[EPB];
    const int tid = threadIdx.x;
    const int row = blockIdx.x * EPB + tid;

    float best = g_best[row];
    int bidx = g_bidx[row];
#pragma unroll
    for (int s = 1; s < SPL; s++) {
        float b = g_best[s * NROWS + row];
        int   i = g_bidx[s * NROWS + row];
        if (b < best) { best = b; bidx = i; }  // strict <: earlier split wins ties
    }

    const float4* wb   = reinterpret_cast<const float4*>(w + (size_t)bidx * D);
    const float4* xrow = reinterpret_cast<const float4*>(x + (size_t)row * D);
    float4* oq = reinterpret_cast<float4*>(out_q + (size_t)row * D);
    float lsum = 0.f;
#pragma unroll
    for (int i = 0; i < 16; i++) {
        float4 wv = wb[i];
        float4 xv = xrow[i];
        float4 dv, ov;
        dv.x = __fsub_rn(wv.x, xv.x);
        dv.y = __fsub_rn(wv.y, xv.y);
        dv.z = __fsub_rn(wv.z, xv.z);
        dv.w = __fsub_rn(wv.w, xv.w);
        ov.x = __fadd_rn(xv.x, dv.x);   // inputs + (quantized - inputs)
        ov.y = __fadd_rn(xv.y, dv.y);
        ov.z = __fadd_rn(xv.z, dv.z);
        ov.w = __fadd_rn(xv.w, dv.w);
        lsum += dv.x * dv.x + dv.y * dv.y + dv.z * dv.z + dv.w * dv.w;
        oq[i] = ov;
    }
    if (has_idx) out_idx[row] = (float)bidx;

    s_red[tid] = lsum;
    __syncthreads();
#pragma unroll
    for (int s = EPB / 2; s > 0; s >>= 1) {
        if (tid < s) s_red[tid] = __fadd_rn(s_red[tid], s_red[tid + s]);
        __syncthreads();
    }
    if (tid == 0) g_partial[blockIdx.x] = s_red[0];
}

// ---- Kernel C: final deterministic reduction -> commitment loss ------------
__global__ void vq_final(float* __restrict__ out_loss) {
    __shared__ float s[64];
    int tid = threadIdx.x;  // 64 threads
    s[tid] = __fadd_rn(g_partial[tid], g_partial[tid + 64]);
    __syncthreads();
    for (int st = 32; st > 0; st >>= 1) {
        if (tid < st) s[tid] = __fadd_rn(s[tid], s[tid + st]);
        __syncthreads();
    }
    if (tid == 0) {
        float mean = s[0] / 2097152.0f;  // exact: power-of-two divisor
        *out_loss = 0.25f * (mean + mean);
    }
}

extern "C" void kernel_launch(void* const* d_in, const int* in_sizes, int n_in,
                              void* d_out, int out_size) {
    const float* x;
    const float* w;
    if (n_in >= 2 && in_sizes[0] == KTOT * D && in_sizes[1] != KTOT * D) {
        w = (const float*)d_in[0];
        x = (const float*)d_in[1];
    } else {
        x = (const float*)d_in[0];
        w = (const float*)d_in[1];
    }

    float* out = (float*)d_out;
    const long ND = (long)NROWS * D;
    if (out_size < ND) return;

    int has_idx  = out_size >= ND + NROWS;
    int has_loss = out_size >= ND + NROWS + 1;

    cudaFuncSetAttribute(vq_main, cudaFuncAttributeMaxDynamicSharedMemorySize, SMEM_ALL);
    vq_main<<<NBLKM, TPB, SMEM_ALL>>>(x, w);
    vq_epi<<<NEPI, EPB>>>(x, w, out, out + ND, has_idx);
    if (has_loss) vq_final<<<1, 64>>>(out + ND + NROWS);
}

// round 13
// speedup vs baseline: 1.3308x; 1.3116x over previous
#include <cuda_runtime.h>

// VectorQuantization: N=32768 rows of D=64 vs K=1024 codes.
// out = [quantized (N*D) | indices as float (N) | commitment_loss (1)]
//
// R13: main kernel is R10 verbatim (best measured: 113us). Epilogue
// re-parallelized: 512 blocks x 64 threads (was 128x256 = 0.86 blocks/SM),
// final reduce over 512 partials. Rounding-critical sequences identical to
// all passing rounds (rel_err 1.19e-7).

#define NROWS 32768
#define D     64
#define RB    128                   // rows per block
#define CBT   64                    // codes per compute tile
#define SPL   8                     // K splits
#define KTOT  1024
#define KPB   (KTOT / SPL)          // 128 codes per block (= 2 tiles, both staged)
#define TILES (KPB / CBT)           // 2
#define TPB   128
#define NBLKM ((NROWS / RB) * SPL)  // 2048
#define EPB   64                    // epilogue threads per block
#define NEPI  (NROWS / EPB)         // 512 epilogue blocks

#define SX_BYTES  (32 * RB * 8)     // 32768: x d-pairs [dp][row]
#define SWD_BYTES (32 * KPB * 8)    // 32768: w d-pairs [dp][code]
#define SXN_OFF   (SX_BYTES + SWD_BYTES)
#define SWN_OFF   (SXN_OFF + RB * 4)
#define SMEM_ALL  (SWN_OFF + KPB * 4)

__device__ float g_best[SPL * NROWS];
__device__ int   g_bidx[SPL * NROWS];
__device__ float g_partial[NEPI];

static __device__ __forceinline__ unsigned long long ffma2(unsigned long long a,
                                                           unsigned long long b,
                                                           unsigned long long c) {
    unsigned long long d;
    asm("fma.rn.f32x2 %0, %1, %2, %3;" : "=l"(d) : "l"(a), "l"(b), "l"(c));
    return d;
}
static __device__ __forceinline__ unsigned long long pack2(float lo, float hi) {
    unsigned long long r;
    asm("mov.b64 %0, {%1, %2};" : "=l"(r) : "f"(lo), "f"(hi));
    return r;
}
static __device__ __forceinline__ void unpack2(unsigned long long v, float& lo, float& hi) {
    asm("mov.b64 {%0, %1}, %2;" : "=f"(lo), "=f"(hi) : "l"(v));
}

// ---- Kernel A: 128-row x 128-code block (R10 verbatim) ---------------------
__global__ void __launch_bounds__(TPB, 2) vq_main(const float* __restrict__ x,
                                                  const float* __restrict__ w) {
    extern __shared__ __align__(16) char smem_raw[];
    unsigned long long* sx  = reinterpret_cast<unsigned long long*>(smem_raw);             // [dp][128 rows]
    unsigned long long* swd = reinterpret_cast<unsigned long long*>(smem_raw + SX_BYTES);  // [dp][128 codes]
    float* sxn = reinterpret_cast<float*>(smem_raw + SXN_OFF);   // [RB]
    float* swn = reinterpret_cast<float*>(smem_raw + SWN_OFF);   // [KPB]
    // merge buffers overlay swd after final sync
    float* m_b = reinterpret_cast<float*>(smem_raw + SX_BYTES);             // [4*RB]
    int*   m_i = reinterpret_cast<int*>(smem_raw + SX_BYTES + 4 * RB * 4);  // [4*RB]

    const int tid   = threadIdx.x;
    const int lane  = tid & 31;
    const int warp  = tid >> 5;          // 0..3: code chunk warp*16 within tile
    const int split = blockIdx.x & (SPL - 1);
    const int row0  = (blockIdx.x >> 3) * RB;
    const int k0    = split * KPB;

    // ---- stage x row tid AND w code row tid, concurrently; one sync ----
    {
        const float4* xr = reinterpret_cast<const float4*>(x + (size_t)(row0 + tid) * D);
        const float4* wrp = reinterpret_cast<const float4*>(w + (size_t)(k0 + tid) * D);
        float sX = 0.f, sW = 0.f;
#pragma unroll
        for (int i = 0; i < 16; i++) {
            float4 v = xr[i];
            sX = __fadd_rn(sX, __fmul_rn(v.x, v.x));
            sX = __fadd_rn(sX, __fmul_rn(v.y, v.y));
            sX = __fadd_rn(sX, __fmul_rn(v.z, v.z));
            sX = __fadd_rn(sX, __fmul_rn(v.w, v.w));
            sx[(2 * i) * RB + tid]     = pack2(v.x, v.y);
            sx[(2 * i + 1) * RB + tid] = pack2(v.z, v.w);
            float4 u = wrp[i];
            sW = __fadd_rn(sW, __fmul_rn(u.x, u.x));
            sW = __fadd_rn(sW, __fmul_rn(u.y, u.y));
            sW = __fadd_rn(sW, __fmul_rn(u.z, u.z));
            sW = __fadd_rn(sW, __fmul_rn(u.w, u.w));
            swd[(2 * i) * KPB + tid]     = pack2(u.x, u.y);
            swd[(2 * i + 1) * KPB + tid] = pack2(u.z, u.w);
        }
        sxn[tid] = sX;
        swn[tid] = sW;
    }
    __syncthreads();

    // thread's 4 rows: 2*lane, 2*lane+1, 64+2*lane, 65+2*lane
    const int rlA = 2 * lane;
    const int rlB = 64 + 2 * lane;
    const float xnr[4] = {sxn[rlA], sxn[rlA + 1], sxn[rlB], sxn[rlB + 1]};

    float bb[4];
    int   bi[4];
#pragma unroll
    for (int r = 0; r < 4; r++) { bb[r] = 3.4e38f; bi[r] = k0; }

    const ulonglong2* sxu = reinterpret_cast<const ulonglong2*>(sx);   // [dp][64 row-pairs]
    const ulonglong2* swu = reinterpret_cast<const ulonglong2*>(swd);  // [dp][64 code-pairs]

#pragma unroll
    for (int tile = 0; tile < TILES; tile++) {
        const int kt = k0 + tile * CBT;

        unsigned long long acc[4][16];
#pragma unroll
        for (int r = 0; r < 4; r++)
#pragma unroll
            for (int c = 0; c < 16; c++) acc[r][c] = 0ull;

#pragma unroll 8
        for (int dp = 0; dp < 32; dp++) {
            // x: 2 full-spread LDS.128 (lane-contiguous 16B, 512B distinct)
            ulonglong2 xa = sxu[dp * 64 + lane];        // rows 2L, 2L+1
            ulonglong2 xb = sxu[dp * 64 + 32 + lane];   // rows 64+2L, 65+2L
            const unsigned long long xv[4] = {xa.x, xa.y, xb.x, xb.y};
            // w: 8 broadcast LDS.128 (all lanes same addr), 16 codes
#pragma unroll
            for (int j = 0; j < 8; j++) {
                ulonglong2 wp = swu[dp * 64 + tile * 32 + warp * 8 + j];
#pragma unroll
                for (int r = 0; r < 4; r++)
                    acc[r][2 * j]     = ffma2(xv[r], wp.x, acc[r][2 * j]);
#pragma unroll
                for (int r = 0; r < 4; r++)
                    acc[r][2 * j + 1] = ffma2(xv[r], wp.y, acc[r][2 * j + 1]);
            }
        }

        // tail: dists + per-thread argmin, codes ascending
#pragma unroll
        for (int c = 0; c < 16; c++) {
            const int cl = warp * 16 + c;
            const float wn = swn[tile * CBT + cl];
            const int cglob = kt + cl;
#pragma unroll
            for (int r = 0; r < 4; r++) {
                float lo, hi;
                unpack2(acc[r][c], lo, hi);
                float dot = __fadd_rn(lo, hi);
                // Reference rounding: (||x||^2 + ||e||^2) - (2.0 * dot).
                float dist = __fsub_rn(__fadd_rn(xnr[r], wn), __fmul_rn(2.0f, dot));
                if (dist < bb[r]) { bb[r] = dist; bi[r] = cglob; }
            }
        }
    }

    // ---- cross-warp merge (warps own disjoint code chunks, same rows) ----
    __syncthreads();  // tails done; safe to overlay swd region
    m_b[warp * RB + rlA]     = bb[0];  m_i[warp * RB + rlA]     = bi[0];
    m_b[warp * RB + rlA + 1] = bb[1];  m_i[warp * RB + rlA + 1] = bi[1];
    m_b[warp * RB + rlB]     = bb[2];  m_i[warp * RB + rlB]     = bi[2];
    m_b[warp * RB + rlB + 1] = bb[3];  m_i[warp * RB + rlB + 1] = bi[3];
    __syncthreads();
    {
        float B = m_b[tid];
        int   I = m_i[tid];
#pragma unroll
        for (int ww = 1; ww < 4; ww++) {
            float b2 = m_b[ww * RB + tid];
            int   i2 = m_i[ww * RB + tid];
            if (b2 < B || (b2 == B && i2 < I)) { B = b2; I = i2; }  // lowest idx ties
        }
        g_best[split * NROWS + row0 + tid] = B;
        g_bidx[split * NROWS + row0 + tid] = I;
    }
}

// ---- Kernel B: reduce splits, gather, STE output, loss partials ------------
// 512 blocks x 64 threads (was 128x256): 3.5 blocks/SM instead of 0.86.
__global__ void __launch_bounds__(EPB) vq_epi(const float* __restrict__ x,
                                              const float* __restrict__ w,
                                              float* __restrict__ out_q,
                                              float* __restrict__ out_idx,
                                              int has_idx) {
    __shared__ float s_red[EPB];
    const int tid = threadIdx.x;
    const int row = blockIdx.x * EPB + tid;

    float best = g_best[row];
    int bidx = g_bidx[row];
#pragma unroll
    for (int s = 1; s < SPL; s++) {
        float b = g_best[s * NROWS + row];
        int   i = g_bidx[s * NROWS + row];
        if (b < best) { best = b; bidx = i; }  // strict <: earlier split wins ties
    }

    const float4* wb   = reinterpret_cast<const float4*>(w + (size_t)bidx * D);
    const float4* xrow = reinterpret_cast<const float4*>(x + (size_t)row * D);
    float4* oq = reinterpret_cast<float4*>(out_q + (size_t)row * D);
    float lsum = 0.f;
#pragma unroll
    for (int i = 0; i < 16; i++) {
        float4 wv = wb[i];
        float4 xv = xrow[i];
        float4 dv, ov;
        dv.x = __fsub_rn(wv.x, xv.x);
        dv.y = __fsub_rn(wv.y, xv.y);
        dv.z = __fsub_rn(wv.z, xv.z);
        dv.w = __fsub_rn(wv.w, xv.w);
        ov.x = __fadd_rn(xv.x, dv.x);   // inputs + (quantized - inputs)
        ov.y = __fadd_rn(xv.y, dv.y);
        ov.z = __fadd_rn(xv.z, dv.z);
        ov.w = __fadd_rn(xv.w, dv.w);
        lsum += dv.x * dv.x + dv.y * dv.y + dv.z * dv.z + dv.w * dv.w;
        oq[i] = ov;
    }
    if (has_idx) out_idx[row] = (float)bidx;

    s_red[tid] = lsum;
    __syncthreads();
#pragma unroll
    for (int s = EPB / 2; s > 0; s >>= 1) {
        if (tid < s) s_red[tid] = __fadd_rn(s_red[tid], s_red[tid + s]);
        __syncthreads();
    }
    if (tid == 0) g_partial[blockIdx.x] = s_red[0];
}

// ---- Kernel C: final deterministic reduction -> commitment loss ------------
__global__ void vq_final(float* __restrict__ out_loss) {
    __shared__ float s[256];
    int tid = threadIdx.x;  // 256 threads over 512 partials
    s[tid] = __fadd_rn(g_partial[tid], g_partial[tid + 256]);
    __syncthreads();
    for (int st = 128; st > 0; st >>= 1) {
        if (tid < st) s[tid] = __fadd_rn(s[tid], s[tid + st]);
        __syncthreads();
    }
    if (tid == 0) {
        float mean = s[0] / 2097152.0f;  // exact: power-of-two divisor
        *out_loss = 0.25f * (mean + mean);
    }
}

extern "C" void kernel_launch(void* const* d_in, const int* in_sizes, int n_in,
                              void* d_out, int out_size) {
    const float* x;
    const float* w;
    if (n_in >= 2 && in_sizes[0] == KTOT * D && in_sizes[1] != KTOT * D) {
        w = (const float*)d_in[0];
        x = (const float*)d_in[1];
    } else {
        x = (const float*)d_in[0];
        w = (const float*)d_in[1];
    }

    float* out = (float*)d_out;
    const long ND = (long)NROWS * D;
    if (out_size < ND) return;

    int has_idx  = out_size >= ND + NROWS;
    int has_loss = out_size >= ND + NROWS + 1;

    cudaFuncSetAttribute(vq_main, cudaFuncAttributeMaxDynamicSharedMemorySize, SMEM_ALL);
    vq_main<<<NBLKM, TPB, SMEM_ALL>>>(x, w);
    vq_epi<<<NEPI, EPB>>>(x, w, out, out + ND, has_idx);
    if (has_loss) vq_final<<<1, 256>>>(out + ND + NROWS);
}